// round 1
// baseline (speedup 1.0000x reference)
#include <cuda_runtime.h>
#include <cstdint>

// Problem constants
#define C_TOT   2048
#define L_TOT   9
#define K_TOT   (C_TOT * L_TOT)     // 18432
#define N_BATCH 4
#define HW      1024                // 32*32
#define NPIX    (N_BATCH * HW)      // 4096
#define O_TOT   256

// ---------------- device scratch (static: no allocation) ----------------
__device__ float g_wt2[K_TOT * O_TOT];       // [ (l*2048+c) ][ o ]   ~18.9MB
__device__ float g_cwt[K_TOT * L_TOT];       // [ (l*2048+c) ][ j ]   ~663KB
__device__ float g_part[18 * L_TOT * NPIX];  // conv partials          ~2.65MB
__device__ float g_sigma[L_TOT * NPIX];      // raw conv output
__device__ float g_smax[L_TOT * NPIX];       // softmax weights s[l][p]
__device__ float g_scale[L_TOT];
__device__ float g_shift[L_TOT];

// ---------------- f32x2 helpers (sm_103a packed fp32) ----------------
__device__ __forceinline__ unsigned long long ffma2(unsigned long long a,
                                                    unsigned long long b,
                                                    unsigned long long c) {
    unsigned long long d;
    asm("fma.rn.f32x2 %0, %1, %2, %3;" : "=l"(d) : "l"(a), "l"(b), "l"(c));
    return d;
}
__device__ __forceinline__ unsigned long long pack2(float lo, float hi) {
    unsigned long long d;
    asm("mov.b64 %0, {%1, %2};" : "=l"(d) : "f"(lo), "f"(hi));
    return d;
}
union F4U { float4 f; unsigned long long u[2]; };
union U2F { unsigned long long u; float2 f; };

// ---------------- kernel 1: transpose weight (O x K) -> wt2 (K' x O) ----------------
// K' row index R = l*2048 + c  where original k = c*9 + l
__global__ __launch_bounds__(256) void transpose_w(const float* __restrict__ w) {
    __shared__ float t[32][33];
    const int k0 = blockIdx.x * 32;
    const int o0 = blockIdx.y * 32;
    const int tx = threadIdx.x, ty = threadIdx.y;   // 32 x 8
#pragma unroll
    for (int s = 0; s < 32; s += 8)
        t[ty + s][tx] = w[(size_t)(o0 + ty + s) * K_TOT + k0 + tx];
    __syncthreads();
#pragma unroll
    for (int s = 0; s < 32; s += 8) {
        int k = k0 + ty + s;
        int c = k / 9;
        int l = k - c * 9;
        g_wt2[(size_t)(l * C_TOT + c) * O_TOT + o0 + tx] = t[tx][ty + s];
    }
}

// ---------------- kernel 2: transpose conv_w (9 x K) -> cwt (K' x 9) ----------------
__global__ __launch_bounds__(256) void transpose_cw(const float* __restrict__ cw) {
    int i = blockIdx.x * 256 + threadIdx.x;     // over K_TOT*9
    if (i < K_TOT * L_TOT) {
        int R = i / 9, j = i - R * 9;
        int l = R >> 11, c = R & 2047;
        g_cwt[i] = cw[(size_t)j * K_TOT + c * 9 + l];
    }
}

// ---------------- kernel 3: conv partials ----------------
// grid: (8 pixel tiles of 512, 18 chunks = 9 l * 2 c-halves), 256 threads, 2 px/thread
__global__ __launch_bounds__(256) void conv_partial(const float* __restrict__ x) {
    __shared__ float cw_sh[8][9];
    const int tid = threadIdx.x;
    const int p0  = blockIdx.x * 512;
    const int l   = blockIdx.y >> 1;
    const int c0  = (blockIdx.y & 1) << 10;     // 0 or 1024
    const int dy  = l / 3 - 1, dx = l % 3 - 1;

    // pixel A = p0+tid, pixel B = p0+tid+256
    int pA = p0 + tid, pB = pA + 256;
    int nA = pA >> 10, remA = pA & 1023, yA = remA >> 5, xA = remA & 31;
    int nB = pB >> 10, remB = pB & 1023, yB = remB >> 5, xB = remB & 31;
    int yyA = yA + dy, xxA = xA + dx;
    int yyB = yB + dy, xxB = xB + dx;
    bool vA = ((unsigned)yyA < 32u) && ((unsigned)xxA < 32u);
    bool vB = ((unsigned)yyB < 32u) && ((unsigned)xxB < 32u);
    const float* ptrA = x + ((size_t)nA << 21) + (yyA << 5) + xxA;
    const float* ptrB = x + ((size_t)nB << 21) + (yyB << 5) + xxB;

    float acc0[9], acc1[9];
#pragma unroll
    for (int j = 0; j < 9; j++) { acc0[j] = 0.f; acc1[j] = 0.f; }

    for (int ct = 0; ct < 1024; ct += 8) {
        __syncthreads();
        if (tid < 72) {
            int kk = tid / 9, j = tid - kk * 9;
            cw_sh[kk][j] = g_cwt[(size_t)(l * C_TOT + c0 + ct + kk) * 9 + j];
        }
        __syncthreads();
#pragma unroll
        for (int kk = 0; kk < 8; kk++) {
            int c = c0 + ct + kk;
            float fA = vA ? ptrA[(size_t)c << 10] : 0.f;
            float fB = vB ? ptrB[(size_t)c << 10] : 0.f;
#pragma unroll
            for (int j = 0; j < 9; j++) {
                acc0[j] += fA * cw_sh[kk][j];
                acc1[j] += fB * cw_sh[kk][j];
            }
        }
    }
    const size_t base = (size_t)blockIdx.y * (L_TOT * NPIX);
#pragma unroll
    for (int j = 0; j < 9; j++) {
        g_part[base + (size_t)j * NPIX + pA] = acc0[j];
        g_part[base + (size_t)j * NPIX + pB] = acc1[j];
    }
}

// ---------------- kernel 4: reduce partials -> sigma ----------------
__global__ __launch_bounds__(256) void conv_reduce() {
    int i = blockIdx.x * 256 + threadIdx.x;   // over 9*4096
    if (i < L_TOT * NPIX) {
        float s = 0.f;
#pragma unroll
        for (int ch = 0; ch < 18; ch++) s += g_part[(size_t)ch * (L_TOT * NPIX) + i];
        g_sigma[i] = s;
    }
}

// ---------------- kernel 5: BN statistics ----------------
__global__ __launch_bounds__(256) void bn_stats(const float* __restrict__ gamma,
                                                const float* __restrict__ beta) {
    __shared__ float shs[256], shq[256];
    const int j = blockIdx.x, tid = threadIdx.x;
    float s = 0.f, q = 0.f;
    for (int i = tid; i < NPIX; i += 256) {
        float v = g_sigma[j * NPIX + i];
        s += v; q += v * v;
    }
    shs[tid] = s; shq[tid] = q;
    __syncthreads();
    for (int st = 128; st > 0; st >>= 1) {
        if (tid < st) { shs[tid] += shs[tid + st]; shq[tid] += shq[tid + st]; }
        __syncthreads();
    }
    if (tid == 0) {
        float mean = shs[0] * (1.f / NPIX);
        float var  = shq[0] * (1.f / NPIX) - mean * mean;
        float inv  = rsqrtf(var + 1e-5f);
        float sc   = gamma[j] * inv;
        g_scale[j] = sc;
        g_shift[j] = beta[j] - mean * sc;
    }
}

// ---------------- kernel 6: softmax over l per pixel ----------------
__global__ __launch_bounds__(256) void softmax_k() {
    int p = blockIdx.x * 256 + threadIdx.x;   // 4096
    float v[9];
    float m = -1e30f;
#pragma unroll
    for (int j = 0; j < 9; j++) {
        v[j] = g_sigma[j * NPIX + p] * g_scale[j] + g_shift[j];
        m = fmaxf(m, v[j]);
    }
    float s = 0.f;
#pragma unroll
    for (int j = 0; j < 9; j++) { v[j] = expf(v[j] - m); s += v[j]; }
    float inv = 1.f / s;
#pragma unroll
    for (int j = 0; j < 9; j++) g_smax[j * NPIX + p] = v[j] * inv;
}

// ---------------- kernel 7: main GEMM (FFMA2 path) ----------------
// out[o,p] = sum_R wt2[R][o] * ( x_shift_{l(R)}[c(R)][p] * s[l(R)][p] )
// Tile: 128 (o) x 64 (p), K-tiles of 8 rows. 256 threads, micro 8o x 4p (4 o-pairs).
__global__ __launch_bounds__(256, 1) void main_gemm(const float* __restrict__ x,
                                                    float* __restrict__ out) {
    __shared__ float a_sh[8][128];
    __shared__ float b_sh[8][64];
    __shared__ float s_sh[9][64];

    const int tid    = threadIdx.x;
    const int p0     = blockIdx.x * 64;
    const int o_base = blockIdx.y * 128;

    for (int i = tid; i < 9 * 64; i += 256) {
        int l = i / 64, pp = i - l * 64;
        s_sh[l][pp] = g_smax[l * NPIX + p0 + pp];
    }
    __syncthreads();

    // A-load geometry: 1 float4 per thread per tile
    const int kkA  = tid >> 5;
    const int aCol = (tid & 31) << 2;
    const float* aptr = g_wt2 + (size_t)kkA * O_TOT + o_base + aCol;

    // B-load geometry: rows kkB and kkB+4, same pixel ppB
    const int kkB = tid >> 6;      // 0..3
    const int ppB = tid & 63;
    const int p   = p0 + ppB;
    const int nB  = p >> 10, remB = p & 1023, yB = remB >> 5, xB = remB & 31;
    const float* xbase = x + ((size_t)nB << 21);

    const int o_local = (tid & 15) << 3;
    const int p_local = (tid >> 4) << 2;

    unsigned long long acc[4][4];
#pragma unroll
    for (int i = 0; i < 4; i++)
#pragma unroll
        for (int jj = 0; jj < 4; jj++) acc[i][jj] = 0ULL;

    float4 av;
    float  bv0, bv1, sf;

    auto LOAD = [&](int kt) {
        av = *(const float4*)(aptr + (size_t)kt * (8 * O_TOT));
        int l  = kt >> 8;                         // 8-row tiles never straddle l
        int yy = yB + (l / 3) - 1;
        int xq = xB + (l % 3) - 1;
        bool valid = ((unsigned)yy < 32u) && ((unsigned)xq < 32u);
        sf = s_sh[l][ppB];
        int c0 = ((kt & 255) << 3) + kkB;
        const float* bp = xbase + (yy << 5) + xq;
        bv0 = valid ? bp[(size_t)c0 << 10]       : 0.f;
        bv1 = valid ? bp[(size_t)(c0 + 4) << 10] : 0.f;
    };

    LOAD(0);
    const int NT = K_TOT / 8;   // 2304
    for (int kt = 0; kt < NT; kt++) {
        __syncthreads();
        *(float4*)&a_sh[kkA][aCol] = av;
        b_sh[kkB][ppB]     = bv0 * sf;
        b_sh[kkB + 4][ppB] = bv1 * sf;
        __syncthreads();
        if (kt + 1 < NT) LOAD(kt + 1);

#pragma unroll
        for (int kk = 0; kk < 8; kk++) {
            F4U A0, A1;
            A0.f = *(const float4*)&a_sh[kk][o_local];
            A1.f = *(const float4*)&a_sh[kk][o_local + 4];
            float4 b = *(const float4*)&b_sh[kk][p_local];
            unsigned long long bb0 = pack2(b.x, b.x);
            unsigned long long bb1 = pack2(b.y, b.y);
            unsigned long long bb2 = pack2(b.z, b.z);
            unsigned long long bb3 = pack2(b.w, b.w);

            acc[0][0] = ffma2(A0.u[0], bb0, acc[0][0]);
            acc[0][1] = ffma2(A0.u[0], bb1, acc[0][1]);
            acc[0][2] = ffma2(A0.u[0], bb2, acc[0][2]);
            acc[0][3] = ffma2(A0.u[0], bb3, acc[0][3]);
            acc[1][0] = ffma2(A0.u[1], bb0, acc[1][0]);
            acc[1][1] = ffma2(A0.u[1], bb1, acc[1][1]);
            acc[1][2] = ffma2(A0.u[1], bb2, acc[1][2]);
            acc[1][3] = ffma2(A0.u[1], bb3, acc[1][3]);
            acc[2][0] = ffma2(A1.u[0], bb0, acc[2][0]);
            acc[2][1] = ffma2(A1.u[0], bb1, acc[2][1]);
            acc[2][2] = ffma2(A1.u[0], bb2, acc[2][2]);
            acc[2][3] = ffma2(A1.u[0], bb3, acc[2][3]);
            acc[3][0] = ffma2(A1.u[1], bb0, acc[3][0]);
            acc[3][1] = ffma2(A1.u[1], bb1, acc[3][1]);
            acc[3][2] = ffma2(A1.u[1], bb2, acc[3][2]);
            acc[3][3] = ffma2(A1.u[1], bb3, acc[3][3]);
        }
    }

    // epilogue: out[(n*256 + o)*1024 + hw]
    const int pg = p0 + p_local;
    const int n2 = pg >> 10;
    const int hw = pg & 1023;
#pragma unroll
    for (int i = 0; i < 4; i++) {
        int o = o_base + o_local + (i << 1);
        U2F t0, t1, t2, t3;
        t0.u = acc[i][0]; t1.u = acc[i][1]; t2.u = acc[i][2]; t3.u = acc[i][3];
        float4 lo4 = make_float4(t0.f.x, t1.f.x, t2.f.x, t3.f.x);
        float4 hi4 = make_float4(t0.f.y, t1.f.y, t2.f.y, t3.f.y);
        *(float4*)&out[((size_t)(n2 * O_TOT + o)     << 10) + hw] = lo4;
        *(float4*)&out[((size_t)(n2 * O_TOT + o + 1) << 10) + hw] = hi4;
    }
}

// ---------------- launch ----------------
extern "C" void kernel_launch(void* const* d_in, const int* in_sizes, int n_in,
                              void* d_out, int out_size) {
    const float* x      = (const float*)d_in[0];
    const float* conv_w = (const float*)d_in[1];
    const float* gamma  = (const float*)d_in[2];
    const float* beta   = (const float*)d_in[3];
    const float* weight = (const float*)d_in[4];
    float* out = (float*)d_out;

    transpose_w <<<dim3(K_TOT / 32, O_TOT / 32), dim3(32, 8)>>>(weight);
    transpose_cw<<<(K_TOT * L_TOT + 255) / 256, 256>>>(conv_w);
    conv_partial<<<dim3(8, 18), 256>>>(x);
    conv_reduce <<<(L_TOT * NPIX + 255) / 256, 256>>>();
    bn_stats    <<<9, 256>>>(gamma, beta);
    softmax_k   <<<NPIX / 256, 256>>>();
    main_gemm   <<<dim3(NPIX / 64, 2), 256>>>(x, out);
}

// round 3
// speedup vs baseline: 4.1286x; 4.1286x over previous
#include <cuda_runtime.h>
#include <cuda_bf16.h>
#include <cstdint>

// ---------------- problem constants ----------------
#define C_TOT   2048
#define L_TOT   9
#define K_TOT   (C_TOT * L_TOT)     // 18432
#define NPIX    4096                // 4*32*32
#define O_TOT   256

// ---------------- GEMM tiling ----------------
#define N_TILE   64                 // pixels per CTA
#define M_TILE   128                // o rows per CTA
#define K_CHUNK  32
#define NCHUNK   (K_TOT / K_CHUNK)  // 576

// ---------------- device scratch ----------------
__device__ __nv_bfloat16 g_a_hi[O_TOT * K_TOT];   // [o][l*2048+c]
__device__ __nv_bfloat16 g_a_lo[O_TOT * K_TOT];
__device__ float g_cwt[K_TOT * L_TOT];
__device__ float g_part[18 * L_TOT * NPIX];
__device__ float g_sigma[L_TOT * NPIX];
__device__ float g_smax[L_TOT * NPIX];
__device__ float g_scale[L_TOT];
__device__ float g_shift[L_TOT];

// ---------------- helpers ----------------
__device__ __forceinline__ uint32_t smem_u32(const void* p) {
    uint32_t a;
    asm("{ .reg .u64 t; cvta.to.shared.u64 t, %1; cvt.u32.u64 %0, t; }" : "=r"(a) : "l"(p));
    return a;
}
__device__ __forceinline__ void ldsm4(uint32_t* r, uint32_t addr) {
    asm volatile("ldmatrix.sync.aligned.m8n8.x4.shared.b16 {%0,%1,%2,%3}, [%4];"
        : "=r"(r[0]), "=r"(r[1]), "=r"(r[2]), "=r"(r[3]) : "r"(addr));
}
__device__ __forceinline__ void mma16816(float* d, const uint32_t* a, const uint32_t* b) {
    asm volatile(
        "mma.sync.aligned.m16n8k16.row.col.f32.bf16.bf16.f32 "
        "{%0,%1,%2,%3}, {%4,%5,%6,%7}, {%8,%9}, {%0,%1,%2,%3};"
        : "+f"(d[0]), "+f"(d[1]), "+f"(d[2]), "+f"(d[3])
        : "r"(a[0]), "r"(a[1]), "r"(a[2]), "r"(a[3]), "r"(b[0]), "r"(b[1]));
}
#define STS128(r0, r1, r2, r3, addr) \
    asm volatile("st.shared.v4.b32 [%0], {%1, %2, %3, %4};" \
        :: "r"((uint32_t)(addr)), "r"(r0), "r"(r1), "r"(r2), "r"(r3) : "memory")
__device__ __forceinline__ uint32_t pkbf(__nv_bfloat16 a, __nv_bfloat16 b) {
    return (uint32_t)__bfloat16_as_ushort(a) | ((uint32_t)__bfloat16_as_ushort(b) << 16);
}

// ---------------- SMEM layout (dynamic) ----------------
// row pad: 40 bf16 = 80B per 32-k row  (80*r mod 128 covers all 8 16B windows)
#define A_ROW_B   80
#define B_ROW_B   80
#define A_TILE_B  (M_TILE * A_ROW_B)      // 10240
#define B_TILE_B  (N_TILE * B_ROW_B)      // 5120
#define OFF_S     0u
#define OFF_A     2560u                   // after 9*64 floats
#define OFF_B     (OFF_A + 4u * A_TILE_B) // 2 buf x {hi,lo}
#define SMEM_BYTES (OFF_B + 4u * B_TILE_B)

// ================= A prep: weight fp32 -> bf16 hi/lo, [o][l*2048+c] =================
__global__ __launch_bounds__(256) void prep_a(const float* __restrict__ w) {
    int t = blockIdx.x * 256 + threadIdx.x;     // O_TOT*C_TOT
    int o = t >> 11, c = t & 2047;
    const float* src = w + (size_t)o * K_TOT + c * 9;
#pragma unroll
    for (int l = 0; l < 9; l++) {
        float v = src[l];
        __nv_bfloat16 h = __float2bfloat16(v);
        __nv_bfloat16 lo = __float2bfloat16(v - __bfloat162float(h));
        size_t di = (size_t)o * K_TOT + l * C_TOT + c;
        g_a_hi[di] = h;
        g_a_lo[di] = lo;
    }
}

// ================= conv path (unchanged, passing) =================
__global__ __launch_bounds__(256) void transpose_cw(const float* __restrict__ cw) {
    int i = blockIdx.x * 256 + threadIdx.x;
    if (i < K_TOT * L_TOT) {
        int R = i / 9, j = i - R * 9;
        int l = R >> 11, c = R & 2047;
        g_cwt[i] = cw[(size_t)j * K_TOT + c * 9 + l];
    }
}

__global__ __launch_bounds__(256) void conv_partial(const float* __restrict__ x) {
    __shared__ float cw_sh[8][9];
    const int tid = threadIdx.x;
    const int p0  = blockIdx.x * 512;
    const int l   = blockIdx.y >> 1;
    const int c0  = (blockIdx.y & 1) << 10;
    const int dy  = l / 3 - 1, dx = l % 3 - 1;

    int pA = p0 + tid, pB = pA + 256;
    int nA = pA >> 10, remA = pA & 1023, yA = remA >> 5, xA = remA & 31;
    int nB = pB >> 10, remB = pB & 1023, yB = remB >> 5, xB = remB & 31;
    int yyA = yA + dy, xxA = xA + dx;
    int yyB = yB + dy, xxB = xB + dx;
    bool vA = ((unsigned)yyA < 32u) && ((unsigned)xxA < 32u);
    bool vB = ((unsigned)yyB < 32u) && ((unsigned)xxB < 32u);
    const float* ptrA = x + ((size_t)nA << 21) + (yyA << 5) + xxA;
    const float* ptrB = x + ((size_t)nB << 21) + (yyB << 5) + xxB;

    float acc0[9], acc1[9];
#pragma unroll
    for (int j = 0; j < 9; j++) { acc0[j] = 0.f; acc1[j] = 0.f; }

    for (int ct = 0; ct < 1024; ct += 8) {
        __syncthreads();
        if (tid < 72) {
            int kk = tid / 9, j = tid - kk * 9;
            cw_sh[kk][j] = g_cwt[(size_t)(l * C_TOT + c0 + ct + kk) * 9 + j];
        }
        __syncthreads();
#pragma unroll
        for (int kk = 0; kk < 8; kk++) {
            int c = c0 + ct + kk;
            float fA = vA ? ptrA[(size_t)c << 10] : 0.f;
            float fB = vB ? ptrB[(size_t)c << 10] : 0.f;
#pragma unroll
            for (int j = 0; j < 9; j++) {
                acc0[j] += fA * cw_sh[kk][j];
                acc1[j] += fB * cw_sh[kk][j];
            }
        }
    }
    const size_t base = (size_t)blockIdx.y * (L_TOT * NPIX);
#pragma unroll
    for (int j = 0; j < 9; j++) {
        g_part[base + (size_t)j * NPIX + pA] = acc0[j];
        g_part[base + (size_t)j * NPIX + pB] = acc1[j];
    }
}

__global__ __launch_bounds__(256) void conv_reduce() {
    int i = blockIdx.x * 256 + threadIdx.x;
    if (i < L_TOT * NPIX) {
        float s = 0.f;
#pragma unroll
        for (int ch = 0; ch < 18; ch++) s += g_part[(size_t)ch * (L_TOT * NPIX) + i];
        g_sigma[i] = s;
    }
}

__global__ __launch_bounds__(256) void bn_stats(const float* __restrict__ gamma,
                                                const float* __restrict__ beta) {
    __shared__ float shs[256], shq[256];
    const int j = blockIdx.x, tid = threadIdx.x;
    float s = 0.f, q = 0.f;
    for (int i = tid; i < NPIX; i += 256) {
        float v = g_sigma[j * NPIX + i];
        s += v; q += v * v;
    }
    shs[tid] = s; shq[tid] = q;
    __syncthreads();
    for (int st = 128; st > 0; st >>= 1) {
        if (tid < st) { shs[tid] += shs[tid + st]; shq[tid] += shq[tid + st]; }
        __syncthreads();
    }
    if (tid == 0) {
        float mean = shs[0] * (1.f / NPIX);
        float var  = shq[0] * (1.f / NPIX) - mean * mean;
        float inv  = rsqrtf(var + 1e-5f);
        float sc   = gamma[j] * inv;
        g_scale[j] = sc;
        g_shift[j] = beta[j] - mean * sc;
    }
}

__global__ __launch_bounds__(256) void softmax_k() {
    int p = blockIdx.x * 256 + threadIdx.x;
    float v[9];
    float m = -1e30f;
#pragma unroll
    for (int j = 0; j < 9; j++) {
        v[j] = g_sigma[j * NPIX + p] * g_scale[j] + g_shift[j];
        m = fmaxf(m, v[j]);
    }
    float s = 0.f;
#pragma unroll
    for (int j = 0; j < 9; j++) { v[j] = expf(v[j] - m); s += v[j]; }
    float inv = 1.f / s;
#pragma unroll
    for (int j = 0; j < 9; j++) g_smax[j * NPIX + p] = v[j] * inv;
}

// ================= main GEMM: mma.sync bf16, 3-term split =================
// grid (NPIX/64, O_TOT/128) = (64, 2); 256 threads = 8 warps; warp tile 32x32
__global__ __launch_bounds__(256, 2) void gemm_mma(const float* __restrict__ x,
                                                   float* __restrict__ out) {
    extern __shared__ char smem_raw[];
    const uint32_t base = smem_u32(smem_raw);
    float* s_sh = (float*)smem_raw;                 // 9*64 softmax

    const int tid  = threadIdx.x;
    const int lane = tid & 31;
    const int wid  = tid >> 5;
    const int warp_m = wid & 3;                      // 4 warps along o
    const int warp_n = wid >> 2;                     // 2 warps along p
    const int p0     = blockIdx.x * N_TILE;
    const int o_base = blockIdx.y * M_TILE;
    const int n_img  = p0 >> 10;

    for (int i = tid; i < 9 * N_TILE; i += 256) {
        int l = i >> 6, pp = i & 63;
        s_sh[i] = g_smax[l * NPIX + p0 + pp];
    }
    __syncthreads();

    // ---- per-thread geometry ----
    // global A loads: u = it*256+tid -> row = u>>2, c16 = u&3
    // B production: pixel pp, k sub-block jg (8 k's)
    const int pp = tid & 63;
    const int jg = tid >> 6;
    const int y0 = ((p0 & 1023) >> 5) + (pp >> 5);
    const int x0 = pp & 31;
    const float* xn = x + ((size_t)n_img << 21);

    // ldmatrix address geometry
    const uint32_t aRow  = (uint32_t)(warp_m * 32 + (lane & 15));
    const uint32_t aColB = (uint32_t)(((lane >> 4) & 1) * 16);
    const uint32_t bRow  = (uint32_t)(warp_n * 32 + ((lane >> 4) & 1) * 8 + (lane & 7));
    const uint32_t bColB = (uint32_t)(((lane >> 3) & 1) * 16);

    float acc[2][4][4];
#pragma unroll
    for (int a = 0; a < 2; a++)
#pragma unroll
        for (int b = 0; b < 4; b++)
#pragma unroll
            for (int c = 0; c < 4; c++) acc[a][b][c] = 0.f;

    uint4 paH[2], paL[2];
    float pv[8];
    float psf;

    auto LOADC = [&](int kt) {
#pragma unroll
        for (int it = 0; it < 2; it++) {
            int u = it * 256 + tid;
            int row = u >> 2, c16 = u & 3;
            size_t g = (size_t)(o_base + row) * K_TOT + (size_t)kt * 32 + c16 * 8;
            paH[it] = *(const uint4*)(g_a_hi + g);
            paL[it] = *(const uint4*)(g_a_lo + g);
        }
        int l  = kt >> 6;
        int c0 = (kt & 63) * 32 + jg * 8;
        int dy = l / 3 - 1, dx = l % 3 - 1;
        int yy = y0 + dy, xc = x0 + dx;
        bool valid = ((unsigned)yy < 32u) & ((unsigned)xc < 32u);
        psf = s_sh[l * 64 + pp];
        const float* bp = xn + ((size_t)c0 << 10) + (yy << 5) + xc;
#pragma unroll
        for (int j = 0; j < 8; j++) pv[j] = valid ? bp[(size_t)j << 10] : 0.f;
    };

    auto STOREC = [&](int buf) {
        uint32_t aBase = base + OFF_A + (uint32_t)buf * 2u * A_TILE_B;
#pragma unroll
        for (int it = 0; it < 2; it++) {
            int u = it * 256 + tid;
            uint32_t row = (uint32_t)(u >> 2), c16 = (uint32_t)(u & 3);
            uint32_t so = aBase + row * A_ROW_B + c16 * 16;
            STS128(paH[it].x, paH[it].y, paH[it].z, paH[it].w, so);
            STS128(paL[it].x, paL[it].y, paL[it].z, paL[it].w, so + A_TILE_B);
        }
        uint32_t hp[4], lp[4];
#pragma unroll
        for (int q = 0; q < 4; q++) {
            float f0 = pv[2 * q] * psf, f1 = pv[2 * q + 1] * psf;
            __nv_bfloat16 h0 = __float2bfloat16(f0);
            __nv_bfloat16 h1 = __float2bfloat16(f1);
            __nv_bfloat16 g0 = __float2bfloat16(f0 - __bfloat162float(h0));
            __nv_bfloat16 g1 = __float2bfloat16(f1 - __bfloat162float(h1));
            hp[q] = pkbf(h0, h1);
            lp[q] = pkbf(g0, g1);
        }
        uint32_t bBase = base + OFF_B + (uint32_t)buf * 2u * B_TILE_B
                       + (uint32_t)pp * B_ROW_B + (uint32_t)jg * 16;
        STS128(hp[0], hp[1], hp[2], hp[3], bBase);
        STS128(lp[0], lp[1], lp[2], lp[3], bBase + B_TILE_B);
    };

    auto COMPUTE = [&](int buf) {
        uint32_t aB = base + OFF_A + (uint32_t)buf * 2u * A_TILE_B;
        uint32_t bB = base + OFF_B + (uint32_t)buf * 2u * B_TILE_B;
#pragma unroll
        for (int ks = 0; ks < 2; ks++) {
            uint32_t aH[2][4], aL[2][4], bH[2][4], bL[2][4];
#pragma unroll
            for (int ms = 0; ms < 2; ms++) {
                uint32_t ad = aB + (aRow + ms * 16) * A_ROW_B + aColB + ks * 32;
                ldsm4(aH[ms], ad);
                ldsm4(aL[ms], ad + A_TILE_B);
            }
#pragma unroll
            for (int np = 0; np < 2; np++) {
                uint32_t bd = bB + (bRow + np * 16) * B_ROW_B + bColB + ks * 32;
                ldsm4(bH[np], bd);
                ldsm4(bL[np], bd + B_TILE_B);
            }
#pragma unroll
            for (int ms = 0; ms < 2; ms++)
#pragma unroll
                for (int ns = 0; ns < 4; ns++) {
                    const int np = ns >> 1, half = (ns & 1) * 2;
                    mma16816(acc[ms][ns], aH[ms], &bH[np][half]);
                    mma16816(acc[ms][ns], aH[ms], &bL[np][half]);
                    mma16816(acc[ms][ns], aL[ms], &bH[np][half]);
                }
        }
    };

    LOADC(0);
    STOREC(0);
    __syncthreads();

    for (int kt = 0; kt < NCHUNK; kt++) {
        const int buf = kt & 1;
        if (kt + 1 < NCHUNK) LOADC(kt + 1);
        COMPUTE(buf);
        if (kt + 1 < NCHUNK) STOREC(buf ^ 1);
        __syncthreads();
    }

    // ---- epilogue ----
    const int hw0 = (p0 & 1023);
#pragma unroll
    for (int ms = 0; ms < 2; ms++)
#pragma unroll
        for (int ns = 0; ns < 4; ns++) {
            int row  = o_base + warp_m * 32 + ms * 16 + (lane >> 2);
            int coln = hw0 + warp_n * 32 + ns * 8 + (lane & 3) * 2;
            float* p1 = out + (((size_t)(n_img * O_TOT + row)) << 10) + coln;
            *(float2*)p1 = make_float2(acc[ms][ns][0], acc[ms][ns][1]);
            float* p2 = p1 + ((size_t)8 << 10);
            *(float2*)p2 = make_float2(acc[ms][ns][2], acc[ms][ns][3]);
        }
}

// ---------------- launch ----------------
extern "C" void kernel_launch(void* const* d_in, const int* in_sizes, int n_in,
                              void* d_out, int out_size) {
    const float* x      = (const float*)d_in[0];
    const float* conv_w = (const float*)d_in[1];
    const float* gamma  = (const float*)d_in[2];
    const float* beta   = (const float*)d_in[3];
    const float* weight = (const float*)d_in[4];
    float* out = (float*)d_out;

    cudaFuncSetAttribute(gemm_mma, cudaFuncAttributeMaxDynamicSharedMemorySize, SMEM_BYTES);

    prep_a      <<<(O_TOT * C_TOT) / 256, 256>>>(weight);
    transpose_cw<<<(K_TOT * L_TOT + 255) / 256, 256>>>(conv_w);
    conv_partial<<<dim3(8, 18), 256>>>(x);
    conv_reduce <<<(L_TOT * NPIX + 255) / 256, 256>>>();
    bn_stats    <<<9, 256>>>(gamma, beta);
    softmax_k   <<<NPIX / 256, 256>>>();
    gemm_mma    <<<dim3(NPIX / N_TILE, O_TOT / M_TILE), 256, SMEM_BYTES>>>(x, out);
}

// round 4
// speedup vs baseline: 5.0433x; 1.2215x over previous
#include <cuda_runtime.h>
#include <cuda_fp16.h>
#include <cstdint>

// ---------------- problem constants ----------------
#define C_TOT   2048
#define L_TOT   9
#define K_TOT   (C_TOT * L_TOT)     // 18432
#define NPIX    4096
#define O_TOT   256

// ---------------- GEMM tiling ----------------
#define N_TILE   64
#define M_TILE   128
#define K_CHUNK  64
#define NCHUNK   (K_TOT / K_CHUNK)  // 288

// ---------------- device scratch ----------------
__device__ __half g_a[O_TOT * K_TOT];             // A fp16, [o][l*2048+c]
__device__ float g_cwt[K_TOT * L_TOT];
__device__ float g_part[18 * L_TOT * NPIX];
__device__ float g_sigma[L_TOT * NPIX];
__device__ float g_smax[L_TOT * NPIX];
__device__ float g_scale[L_TOT];
__device__ float g_shift[L_TOT];

// ---------------- helpers ----------------
__device__ __forceinline__ uint32_t smem_u32(const void* p) {
    uint32_t a;
    asm("{ .reg .u64 t; cvta.to.shared.u64 t, %1; cvt.u32.u64 %0, t; }" : "=r"(a) : "l"(p));
    return a;
}
__device__ __forceinline__ void ldsm4(uint32_t* r, uint32_t addr) {
    asm volatile("ldmatrix.sync.aligned.m8n8.x4.shared.b16 {%0,%1,%2,%3}, [%4];"
        : "=r"(r[0]), "=r"(r[1]), "=r"(r[2]), "=r"(r[3]) : "r"(addr));
}
__device__ __forceinline__ void mma16816(float* d, const uint32_t* a, const uint32_t* b) {
    asm volatile(
        "mma.sync.aligned.m16n8k16.row.col.f32.f16.f16.f32 "
        "{%0,%1,%2,%3}, {%4,%5,%6,%7}, {%8,%9}, {%0,%1,%2,%3};"
        : "+f"(d[0]), "+f"(d[1]), "+f"(d[2]), "+f"(d[3])
        : "r"(a[0]), "r"(a[1]), "r"(a[2]), "r"(a[3]), "r"(b[0]), "r"(b[1]));
}
#define STS128(r0, r1, r2, r3, addr) \
    asm volatile("st.shared.v4.b32 [%0], {%1, %2, %3, %4};" \
        :: "r"((uint32_t)(addr)), "r"(r0), "r"(r1), "r"(r2), "r"(r3) : "memory")
__device__ __forceinline__ uint32_t pkhf(__half a, __half b) {
    return (uint32_t)__half_as_ushort(a) | ((uint32_t)__half_as_ushort(b) << 16);
}
__device__ __forceinline__ unsigned long long ffma2(unsigned long long a,
                                                    unsigned long long b,
                                                    unsigned long long c) {
    unsigned long long d;
    asm("fma.rn.f32x2 %0, %1, %2, %3;" : "=l"(d) : "l"(a), "l"(b), "l"(c));
    return d;
}
__device__ __forceinline__ unsigned long long pack2(float lo, float hi) {
    unsigned long long d;
    asm("mov.b64 %0, {%1, %2};" : "=l"(d) : "f"(lo), "f"(hi));
    return d;
}
union U2F { unsigned long long u; float2 f; };

// ---------------- GEMM SMEM layout ----------------
#define ROW_B     144u                      // 64 fp16 = 128B + 16B pad (conflict-free)
#define A_TILE_B  (128u * ROW_B)            // 18432
#define B_TILE_B  (64u * ROW_B)             // 9216
#define BUF_B     (A_TILE_B + 2u * B_TILE_B)
#define OFF_A     2304u                     // after 9*64 softmax floats
#define SMEM_GEMM (OFF_A + 2u * BUF_B)      // 76032

// ================= A prep: weight fp32 -> fp16, [o][l*2048+c] =================
__global__ __launch_bounds__(256) void prep_a(const float* __restrict__ w) {
    int t = blockIdx.x * 256 + threadIdx.x;     // O_TOT*C_TOT
    int o = t >> 11, c = t & 2047;
    const float* src = w + (size_t)o * K_TOT + c * 9;
#pragma unroll
    for (int l = 0; l < 9; l++)
        g_a[(size_t)o * K_TOT + l * C_TOT + c] = __float2half_rn(src[l]);
}

// ================= conv path =================
__global__ __launch_bounds__(256) void transpose_cw(const float* __restrict__ cw) {
    int i = blockIdx.x * 256 + threadIdx.x;
    if (i < K_TOT * L_TOT) {
        int R = i / 9, j = i - R * 9;
        int l = R >> 11, c = R & 2047;
        g_cwt[i] = cw[(size_t)j * K_TOT + c * 9 + l];
    }
}

// grid (8, 18): 512-pixel tiles x (l, c-half). No inner barriers; cw slice cached
// in smem pre-duplicated as f32x2; accumulate with packed fma.rn.f32x2 (2 pixels).
__global__ __launch_bounds__(256) void conv_partial(const float* __restrict__ x) {
    extern __shared__ char cvsm[];
    unsigned long long* cw2 = (unsigned long long*)cvsm;   // [1024*9]
    const int tid = threadIdx.x;
    const int p0  = blockIdx.x * 512;
    const int l   = blockIdx.y >> 1;
    const int c0  = (blockIdx.y & 1) << 10;
    const int dy  = l / 3 - 1, dx = l % 3 - 1;

    const float* src = g_cwt + (size_t)(l * C_TOT + c0) * 9;
    for (int i = tid; i < 1024 * 9; i += 256) {
        float v = src[i];
        cw2[i] = pack2(v, v);
    }

    int pA = p0 + tid, pB = pA + 256;
    int nA = pA >> 10, remA = pA & 1023, yA = remA >> 5, xA = remA & 31;
    int nB = pB >> 10, remB = pB & 1023, yB = remB >> 5, xB = remB & 31;
    int yyA = yA + dy, xxA = xA + dx;
    int yyB = yB + dy, xxB = xB + dx;
    bool vA = ((unsigned)yyA < 32u) && ((unsigned)xxA < 32u);
    bool vB = ((unsigned)yyB < 32u) && ((unsigned)xxB < 32u);
    const float* ptrA = x + ((size_t)nA << 21) + (yyA << 5) + xxA;
    const float* ptrB = x + ((size_t)nB << 21) + (yyB << 5) + xxB;
    __syncthreads();

    unsigned long long acc[9];
#pragma unroll
    for (int j = 0; j < 9; j++) acc[j] = 0ULL;

#pragma unroll 4
    for (int ct = 0; ct < 1024; ct++) {
        int c = c0 + ct;
        float fA = vA ? ptrA[(size_t)c << 10] : 0.f;
        float fB = vB ? ptrB[(size_t)c << 10] : 0.f;
        unsigned long long pk = pack2(fA, fB);
#pragma unroll
        for (int j = 0; j < 9; j++)
            acc[j] = ffma2(pk, cw2[ct * 9 + j], acc[j]);
    }
    const size_t base = (size_t)blockIdx.y * (L_TOT * NPIX);
#pragma unroll
    for (int j = 0; j < 9; j++) {
        U2F u; u.u = acc[j];
        g_part[base + (size_t)j * NPIX + pA] = u.f.x;
        g_part[base + (size_t)j * NPIX + pB] = u.f.y;
    }
}

__global__ __launch_bounds__(256) void conv_reduce() {
    int i = blockIdx.x * 256 + threadIdx.x;
    if (i < L_TOT * NPIX) {
        float s = 0.f;
#pragma unroll
        for (int ch = 0; ch < 18; ch++) s += g_part[(size_t)ch * (L_TOT * NPIX) + i];
        g_sigma[i] = s;
    }
}

__global__ __launch_bounds__(256) void bn_stats(const float* __restrict__ gamma,
                                                const float* __restrict__ beta) {
    __shared__ float shs[256], shq[256];
    const int j = blockIdx.x, tid = threadIdx.x;
    float s = 0.f, q = 0.f;
    for (int i = tid; i < NPIX; i += 256) {
        float v = g_sigma[j * NPIX + i];
        s += v; q += v * v;
    }
    shs[tid] = s; shq[tid] = q;
    __syncthreads();
    for (int st = 128; st > 0; st >>= 1) {
        if (tid < st) { shs[tid] += shs[tid + st]; shq[tid] += shq[tid + st]; }
        __syncthreads();
    }
    if (tid == 0) {
        float mean = shs[0] * (1.f / NPIX);
        float var  = shq[0] * (1.f / NPIX) - mean * mean;
        float inv  = rsqrtf(var + 1e-5f);
        float sc   = gamma[j] * inv;
        g_scale[j] = sc;
        g_shift[j] = beta[j] - mean * sc;
    }
}

__global__ __launch_bounds__(256) void softmax_k() {
    int p = blockIdx.x * 256 + threadIdx.x;
    float v[9];
    float m = -1e30f;
#pragma unroll
    for (int j = 0; j < 9; j++) {
        v[j] = g_sigma[j * NPIX + p] * g_scale[j] + g_shift[j];
        m = fmaxf(m, v[j]);
    }
    float s = 0.f;
#pragma unroll
    for (int j = 0; j < 9; j++) { v[j] = expf(v[j] - m); s += v[j]; }
    float inv = 1.f / s;
#pragma unroll
    for (int j = 0; j < 9; j++) g_smax[j * NPIX + p] = v[j] * inv;
}

// ================= main GEMM: mma.sync fp16, 2-term B split =================
// grid (64, 2); 256 threads = 8 warps (4 m x 2 n); warp tile 32x32; K_CHUNK=64
__global__ __launch_bounds__(256, 1) void gemm_mma(const float* __restrict__ x,
                                                   float* __restrict__ out) {
    extern __shared__ char smem_raw[];
    const uint32_t base = smem_u32(smem_raw);
    float* s_sh = (float*)smem_raw;                 // 9*64 softmax

    const int tid  = threadIdx.x;
    const int lane = tid & 31;
    const int wid  = tid >> 5;
    const int warp_m = wid & 3;
    const int warp_n = wid >> 2;
    const int p0     = blockIdx.x * N_TILE;
    const int o_base = blockIdx.y * M_TILE;
    const int n_img  = p0 >> 10;

    for (int i = tid; i < 9 * N_TILE; i += 256) {
        int l = i >> 6, pp = i & 63;
        s_sh[i] = g_smax[l * NPIX + p0 + pp];
    }
    __syncthreads();

    const int pp = tid & 63;
    const int jg = tid >> 6;                        // 4 groups x 16 k each
    const int y0 = ((p0 & 1023) >> 5) + (pp >> 5);
    const int x0 = pp & 31;
    const float* xn = x + ((size_t)n_img << 21);

    const uint32_t aRow  = (uint32_t)(warp_m * 32 + (lane & 15));
    const uint32_t aColB = (uint32_t)(((lane >> 4) & 1) * 16);
    const uint32_t bRow  = (uint32_t)(warp_n * 32 + ((lane >> 4) & 1) * 8 + (lane & 7));
    const uint32_t bColB = (uint32_t)(((lane >> 3) & 1) * 16);

    float acc[2][4][4];
#pragma unroll
    for (int a = 0; a < 2; a++)
#pragma unroll
        for (int b = 0; b < 4; b++)
#pragma unroll
            for (int c = 0; c < 4; c++) acc[a][b][c] = 0.f;

    uint4 pa[4];          // A prefetch: 4 x 16B (fp16)
    float pv[16];         // B x prefetch
    float psf;

    auto LOADC = [&](int kt) {
#pragma unroll
        for (int it = 0; it < 4; it++) {
            int u = it * 256 + tid;                  // 1024 = 128 rows x 8 x16B
            int row = u >> 3, c16 = u & 7;
            size_t g = (size_t)(o_base + row) * K_TOT + (size_t)kt * K_CHUNK + c16 * 8;
            pa[it] = *(const uint4*)(g_a + g);
        }
        int l  = kt >> 5;                            // 288 = 9 l x 32
        int c0 = (kt & 31) * 64 + jg * 16;
        int dy = l / 3 - 1, dx = l % 3 - 1;
        int yy = y0 + dy, xc = x0 + dx;
        bool valid = ((unsigned)yy < 32u) & ((unsigned)xc < 32u);
        psf = s_sh[l * 64 + pp];
        const float* bp = xn + ((size_t)c0 << 10) + (yy << 5) + xc;
#pragma unroll
        for (int j = 0; j < 16; j++) pv[j] = valid ? bp[(size_t)j << 10] : 0.f;
    };

    auto STOREC = [&](int buf) {
        uint32_t aB = base + OFF_A + (uint32_t)buf * BUF_B;
#pragma unroll
        for (int it = 0; it < 4; it++) {
            int u = it * 256 + tid;
            uint32_t so = aB + (uint32_t)(u >> 3) * ROW_B + (uint32_t)(u & 7) * 16;
            STS128(pa[it].x, pa[it].y, pa[it].z, pa[it].w, so);
        }
        uint32_t hp[8], lp[8];
#pragma unroll
        for (int q = 0; q < 8; q++) {
            float f0 = pv[2 * q] * psf, f1 = pv[2 * q + 1] * psf;
            __half h0 = __float2half_rn(f0);
            __half h1 = __float2half_rn(f1);
            __half g0 = __float2half_rn(f0 - __half2float(h0));
            __half g1 = __float2half_rn(f1 - __half2float(h1));
            hp[q] = pkhf(h0, h1);
            lp[q] = pkhf(g0, g1);
        }
        uint32_t bB = aB + A_TILE_B + (uint32_t)pp * ROW_B + (uint32_t)jg * 32;
        STS128(hp[0], hp[1], hp[2], hp[3], bB);
        STS128(hp[4], hp[5], hp[6], hp[7], bB + 16);
        STS128(lp[0], lp[1], lp[2], lp[3], bB + B_TILE_B);
        STS128(lp[4], lp[5], lp[6], lp[7], bB + B_TILE_B + 16);
    };

    auto COMPUTE = [&](int buf) {
        uint32_t aB = base + OFF_A + (uint32_t)buf * BUF_B;
        uint32_t bB = aB + A_TILE_B;
#pragma unroll
        for (int ks = 0; ks < 4; ks++) {
            uint32_t aF[2][4], bH[2][4], bL[2][4];
#pragma unroll
            for (int ms = 0; ms < 2; ms++)
                ldsm4(aF[ms], aB + (aRow + ms * 16) * ROW_B + aColB + ks * 32);
#pragma unroll
            for (int np = 0; np < 2; np++) {
                uint32_t bd = bB + (bRow + np * 16) * ROW_B + bColB + ks * 32;
                ldsm4(bH[np], bd);
                ldsm4(bL[np], bd + B_TILE_B);
            }
#pragma unroll
            for (int ms = 0; ms < 2; ms++)
#pragma unroll
                for (int ns = 0; ns < 4; ns++) {
                    const int np = ns >> 1, half = (ns & 1) * 2;
                    mma16816(acc[ms][ns], aF[ms], &bH[np][half]);
                    mma16816(acc[ms][ns], aF[ms], &bL[np][half]);
                }
        }
    };

    LOADC(0);
    STOREC(0);
    __syncthreads();

    for (int kt = 0; kt < NCHUNK; kt++) {
        const int buf = kt & 1;
        if (kt + 1 < NCHUNK) LOADC(kt + 1);
        COMPUTE(buf);
        if (kt + 1 < NCHUNK) STOREC(buf ^ 1);
        __syncthreads();
    }

    const int hw0 = (p0 & 1023);
#pragma unroll
    for (int ms = 0; ms < 2; ms++)
#pragma unroll
        for (int ns = 0; ns < 4; ns++) {
            int row  = o_base + warp_m * 32 + ms * 16 + (lane >> 2);
            int coln = hw0 + warp_n * 32 + ns * 8 + (lane & 3) * 2;
            float* p1 = out + (((size_t)(n_img * O_TOT + row)) << 10) + coln;
            *(float2*)p1 = make_float2(acc[ms][ns][0], acc[ms][ns][1]);
            float* p2 = p1 + ((size_t)8 << 10);
            *(float2*)p2 = make_float2(acc[ms][ns][2], acc[ms][ns][3]);
        }
}

// ---------------- launch ----------------
extern "C" void kernel_launch(void* const* d_in, const int* in_sizes, int n_in,
                              void* d_out, int out_size) {
    const float* x      = (const float*)d_in[0];
    const float* conv_w = (const float*)d_in[1];
    const float* gamma  = (const float*)d_in[2];
    const float* beta   = (const float*)d_in[3];
    const float* weight = (const float*)d_in[4];
    float* out = (float*)d_out;

    cudaFuncSetAttribute(gemm_mma, cudaFuncAttributeMaxDynamicSharedMemorySize, SMEM_GEMM);
    cudaFuncSetAttribute(conv_partial, cudaFuncAttributeMaxDynamicSharedMemorySize, 1024 * 9 * 8);

    prep_a      <<<(O_TOT * C_TOT) / 256, 256>>>(weight);
    transpose_cw<<<(K_TOT * L_TOT + 255) / 256, 256>>>(conv_w);
    conv_partial<<<dim3(8, 18), 256, 1024 * 9 * 8>>>(x);
    conv_reduce <<<(L_TOT * NPIX + 255) / 256, 256>>>();
    bn_stats    <<<9, 256>>>(gamma, beta);
    softmax_k   <<<NPIX / 256, 256>>>();
    gemm_mma    <<<dim3(NPIX / N_TILE, O_TOT / M_TILE), 256, SMEM_GEMM>>>(x, out);
}

// round 5
// speedup vs baseline: 6.4638x; 1.2817x over previous
#include <cuda_runtime.h>
#include <cuda_fp16.h>
#include <cstdint>

// ---------------- problem constants ----------------
#define C_TOT   2048
#define L_TOT   9
#define K_TOT   (C_TOT * L_TOT)     // 18432
#define NPIX    4096
#define O_TOT   256

// ---------------- GEMM tiling ----------------
#define N_TILE   64
#define M_TILE   128
#define K_CHUNK  64
#define NCHUNK   (K_TOT / K_CHUNK)  // 288

// ---------------- device scratch ----------------
__device__ __half g_a[O_TOT * K_TOT];             // A fp16, [o][l*2048+c]
__device__ float g_cwt[K_TOT * L_TOT];
__device__ float g_part[18 * L_TOT * NPIX];
__device__ float g_sigma[L_TOT * NPIX];
__device__ float g_smax[L_TOT * NPIX];
__device__ float g_scale[L_TOT];
__device__ float g_shift[L_TOT];

// ---------------- helpers ----------------
__device__ __forceinline__ uint32_t smem_u32(const void* p) {
    uint32_t a;
    asm("{ .reg .u64 t; cvta.to.shared.u64 t, %1; cvt.u32.u64 %0, t; }" : "=r"(a) : "l"(p));
    return a;
}
__device__ __forceinline__ void ldsm4(uint32_t* r, uint32_t addr) {
    asm volatile("ldmatrix.sync.aligned.m8n8.x4.shared.b16 {%0,%1,%2,%3}, [%4];"
        : "=r"(r[0]), "=r"(r[1]), "=r"(r[2]), "=r"(r[3]) : "r"(addr));
}
__device__ __forceinline__ void mma16816(float* d, const uint32_t* a, const uint32_t* b) {
    asm volatile(
        "mma.sync.aligned.m16n8k16.row.col.f32.f16.f16.f32 "
        "{%0,%1,%2,%3}, {%4,%5,%6,%7}, {%8,%9}, {%0,%1,%2,%3};"
        : "+f"(d[0]), "+f"(d[1]), "+f"(d[2]), "+f"(d[3])
        : "r"(a[0]), "r"(a[1]), "r"(a[2]), "r"(a[3]), "r"(b[0]), "r"(b[1]));
}
#define STS128(r0, r1, r2, r3, addr) \
    asm volatile("st.shared.v4.b32 [%0], {%1, %2, %3, %4};" \
        :: "r"((uint32_t)(addr)), "r"(r0), "r"(r1), "r"(r2), "r"(r3) : "memory")
#define CP_ASYNC16(dst, src) \
    asm volatile("cp.async.ca.shared.global [%0], [%1], 16;" \
        :: "r"((uint32_t)(dst)), "l"(src) : "memory")
#define CP_COMMIT()  asm volatile("cp.async.commit_group;" ::: "memory")
#define CP_WAIT0()   asm volatile("cp.async.wait_group 0;" ::: "memory")
__device__ __forceinline__ uint32_t pkhf(__half a, __half b) {
    return (uint32_t)__half_as_ushort(a) | ((uint32_t)__half_as_ushort(b) << 16);
}
__device__ __forceinline__ unsigned long long ffma2(unsigned long long a,
                                                    unsigned long long b,
                                                    unsigned long long c) {
    unsigned long long d;
    asm("fma.rn.f32x2 %0, %1, %2, %3;" : "=l"(d) : "l"(a), "l"(b), "l"(c));
    return d;
}
__device__ __forceinline__ unsigned long long pack2(float lo, float hi) {
    unsigned long long d;
    asm("mov.b64 %0, {%1, %2};" : "=l"(d) : "f"(lo), "f"(hi));
    return d;
}
union U2F { unsigned long long u; float2 f; };

// ---------------- GEMM SMEM layout ----------------
#define ROW_B     144u                      // 64 fp16 = 128B + 16B pad (conflict-free)
#define A_TILE_B  (128u * ROW_B)            // 18432
#define B_TILE_B  (64u * ROW_B)             // 9216
#define BUF_B     (A_TILE_B + B_TILE_B)     // 27648
#define OFF_A     2304u                     // after 9*64 softmax floats
#define SMEM_GEMM (OFF_A + 2u * BUF_B)      // 57600

// ================= A prep: weight fp32 -> fp16, [o][l*2048+c] =================
__global__ __launch_bounds__(256) void prep_a(const float* __restrict__ w) {
    int t = blockIdx.x * 256 + threadIdx.x;     // O_TOT*C_TOT
    int o = t >> 11, c = t & 2047;
    const float* src = w + (size_t)o * K_TOT + c * 9;
#pragma unroll
    for (int l = 0; l < 9; l++)
        g_a[(size_t)o * K_TOT + l * C_TOT + c] = __float2half_rn(src[l]);
}

// ================= conv path =================
__global__ __launch_bounds__(256) void transpose_cw(const float* __restrict__ cw) {
    int i = blockIdx.x * 256 + threadIdx.x;
    if (i < K_TOT * L_TOT) {
        int R = i / 9, j = i - R * 9;
        int l = R >> 11, c = R & 2047;
        g_cwt[i] = cw[(size_t)j * K_TOT + c * 9 + l];
    }
}

__global__ __launch_bounds__(256) void conv_partial(const float* __restrict__ x) {
    extern __shared__ char cvsm[];
    unsigned long long* cw2 = (unsigned long long*)cvsm;   // [1024*9]
    const int tid = threadIdx.x;
    const int p0  = blockIdx.x * 512;
    const int l   = blockIdx.y >> 1;
    const int c0  = (blockIdx.y & 1) << 10;
    const int dy  = l / 3 - 1, dx = l % 3 - 1;

    const float* src = g_cwt + (size_t)(l * C_TOT + c0) * 9;
    for (int i = tid; i < 1024 * 9; i += 256) {
        float v = src[i];
        cw2[i] = pack2(v, v);
    }

    int pA = p0 + tid, pB = pA + 256;
    int nA = pA >> 10, remA = pA & 1023, yA = remA >> 5, xA = remA & 31;
    int nB = pB >> 10, remB = pB & 1023, yB = remB >> 5, xB = remB & 31;
    int yyA = yA + dy, xxA = xA + dx;
    int yyB = yB + dy, xxB = xB + dx;
    bool vA = ((unsigned)yyA < 32u) && ((unsigned)xxA < 32u);
    bool vB = ((unsigned)yyB < 32u) && ((unsigned)xxB < 32u);
    const float* ptrA = x + ((size_t)nA << 21) + (yyA << 5) + xxA;
    const float* ptrB = x + ((size_t)nB << 21) + (yyB << 5) + xxB;
    __syncthreads();

    unsigned long long acc[9];
#pragma unroll
    for (int j = 0; j < 9; j++) acc[j] = 0ULL;

#pragma unroll 4
    for (int ct = 0; ct < 1024; ct++) {
        int c = c0 + ct;
        float fA = vA ? ptrA[(size_t)c << 10] : 0.f;
        float fB = vB ? ptrB[(size_t)c << 10] : 0.f;
        unsigned long long pk = pack2(fA, fB);
#pragma unroll
        for (int j = 0; j < 9; j++)
            acc[j] = ffma2(pk, cw2[ct * 9 + j], acc[j]);
    }
    const size_t base = (size_t)blockIdx.y * (L_TOT * NPIX);
#pragma unroll
    for (int j = 0; j < 9; j++) {
        U2F u; u.u = acc[j];
        g_part[base + (size_t)j * NPIX + pA] = u.f.x;
        g_part[base + (size_t)j * NPIX + pB] = u.f.y;
    }
}

__global__ __launch_bounds__(256) void conv_reduce() {
    int i = blockIdx.x * 256 + threadIdx.x;
    if (i < L_TOT * NPIX) {
        float s = 0.f;
#pragma unroll
        for (int ch = 0; ch < 18; ch++) s += g_part[(size_t)ch * (L_TOT * NPIX) + i];
        g_sigma[i] = s;
    }
}

__global__ __launch_bounds__(256) void bn_stats(const float* __restrict__ gamma,
                                                const float* __restrict__ beta) {
    __shared__ float shs[256], shq[256];
    const int j = blockIdx.x, tid = threadIdx.x;
    float s = 0.f, q = 0.f;
    for (int i = tid; i < NPIX; i += 256) {
        float v = g_sigma[j * NPIX + i];
        s += v; q += v * v;
    }
    shs[tid] = s; shq[tid] = q;
    __syncthreads();
    for (int st = 128; st > 0; st >>= 1) {
        if (tid < st) { shs[tid] += shs[tid + st]; shq[tid] += shq[tid + st]; }
        __syncthreads();
    }
    if (tid == 0) {
        float mean = shs[0] * (1.f / NPIX);
        float var  = shq[0] * (1.f / NPIX) - mean * mean;
        float inv  = rsqrtf(var + 1e-5f);
        float sc   = gamma[j] * inv;
        g_scale[j] = sc;
        g_shift[j] = beta[j] - mean * sc;
    }
}

__global__ __launch_bounds__(256) void softmax_k() {
    int p = blockIdx.x * 256 + threadIdx.x;
    float v[9];
    float m = -1e30f;
#pragma unroll
    for (int j = 0; j < 9; j++) {
        v[j] = g_sigma[j * NPIX + p] * g_scale[j] + g_shift[j];
        m = fmaxf(m, v[j]);
    }
    float s = 0.f;
#pragma unroll
    for (int j = 0; j < 9; j++) { v[j] = expf(v[j] - m); s += v[j]; }
    float inv = 1.f / s;
#pragma unroll
    for (int j = 0; j < 9; j++) g_smax[j * NPIX + p] = v[j] * inv;
}

// ================= main GEMM: mma.sync fp16 single-term =================
// grid (64, 2); 256 threads = 8 warps (4 m x 2 n); warp tile 32x32; K_CHUNK=64
// A: gmem -> smem via cp.async (double-buffered). B: regs -> fp16 STS.
__global__ __launch_bounds__(256, 1) void gemm_mma(const float* __restrict__ x,
                                                   float* __restrict__ out) {
    extern __shared__ char smem_raw[];
    const uint32_t base = smem_u32(smem_raw);
    float* s_sh = (float*)smem_raw;                 // 9*64 softmax

    const int tid  = threadIdx.x;
    const int lane = tid & 31;
    const int wid  = tid >> 5;
    const int warp_m = wid & 3;
    const int warp_n = wid >> 2;
    const int p0     = blockIdx.x * N_TILE;
    const int o_base = blockIdx.y * M_TILE;
    const int n_img  = p0 >> 10;

    for (int i = tid; i < 9 * N_TILE; i += 256) {
        int l = i >> 6, pp = i & 63;
        s_sh[i] = g_smax[l * NPIX + p0 + pp];
    }
    __syncthreads();

    const int pp = tid & 63;
    const int jg = tid >> 6;                        // 4 groups x 16 k each
    const int y0 = ((p0 & 1023) >> 5) + (pp >> 5);
    const int x0 = pp & 31;
    const float* xn = x + ((size_t)n_img << 21);

    // A cp.async geometry: thread covers rows (tid>>3)+32*it, col16 tid&7
    const int aRowT = tid >> 3;
    const int aC16  = tid & 7;
    const __half* agbase = g_a + (size_t)(o_base + aRowT) * K_TOT + aC16 * 8;

    const uint32_t aRow  = (uint32_t)(warp_m * 32 + (lane & 15));
    const uint32_t aColB = (uint32_t)(((lane >> 4) & 1) * 16);
    const uint32_t bRow  = (uint32_t)(warp_n * 32 + ((lane >> 4) & 1) * 8 + (lane & 7));
    const uint32_t bColB = (uint32_t)(((lane >> 3) & 1) * 16);

    float acc[2][4][4];
#pragma unroll
    for (int a = 0; a < 2; a++)
#pragma unroll
        for (int b = 0; b < 4; b++)
#pragma unroll
            for (int c = 0; c < 4; c++) acc[a][b][c] = 0.f;

    float pv[16];
    float psf;

    auto CPA = [&](int kt, int buf) {
        uint32_t aB = base + OFF_A + (uint32_t)buf * BUF_B
                    + (uint32_t)aRowT * ROW_B + (uint32_t)aC16 * 16;
        const __half* g = agbase + (size_t)kt * K_CHUNK;
#pragma unroll
        for (int it = 0; it < 4; it++)
            CP_ASYNC16(aB + (uint32_t)it * 32u * ROW_B, g + (size_t)it * 32 * K_TOT);
        CP_COMMIT();
    };

    auto LOADB = [&](int kt) {
        int l  = kt >> 5;                            // 288 = 9 l x 32
        int c0 = (kt & 31) * 64 + jg * 16;
        int dy = l / 3 - 1, dx = l % 3 - 1;
        int yy = y0 + dy, xc = x0 + dx;
        bool valid = ((unsigned)yy < 32u) & ((unsigned)xc < 32u);
        psf = s_sh[l * 64 + pp];
        const float* bp = xn + ((size_t)c0 << 10) + (yy << 5) + xc;
#pragma unroll
        for (int j = 0; j < 16; j++) pv[j] = valid ? bp[(size_t)j << 10] : 0.f;
    };

    auto STOREB = [&](int buf) {
        uint32_t hp[8];
#pragma unroll
        for (int q = 0; q < 8; q++) {
            float f0 = pv[2 * q] * psf, f1 = pv[2 * q + 1] * psf;
            hp[q] = pkhf(__float2half_rn(f0), __float2half_rn(f1));
        }
        uint32_t bB = base + OFF_A + (uint32_t)buf * BUF_B + A_TILE_B
                    + (uint32_t)pp * ROW_B + (uint32_t)jg * 32;
        STS128(hp[0], hp[1], hp[2], hp[3], bB);
        STS128(hp[4], hp[5], hp[6], hp[7], bB + 16);
    };

    auto COMPUTE = [&](int buf) {
        uint32_t aB = base + OFF_A + (uint32_t)buf * BUF_B;
        uint32_t bB = aB + A_TILE_B;
#pragma unroll
        for (int ks = 0; ks < 4; ks++) {
            uint32_t aF[2][4], bF[2][4];
#pragma unroll
            for (int ms = 0; ms < 2; ms++)
                ldsm4(aF[ms], aB + (aRow + ms * 16) * ROW_B + aColB + ks * 32);
#pragma unroll
            for (int np = 0; np < 2; np++)
                ldsm4(bF[np], bB + (bRow + np * 16) * ROW_B + bColB + ks * 32);
#pragma unroll
            for (int ms = 0; ms < 2; ms++)
#pragma unroll
                for (int ns = 0; ns < 4; ns++)
                    mma16816(acc[ms][ns], aF[ms], &bF[ns >> 1][(ns & 1) * 2]);
        }
    };

    CPA(0, 0);
    LOADB(0);
    STOREB(0);
    CP_WAIT0();
    __syncthreads();

    for (int kt = 0; kt < NCHUNK; kt++) {
        const int buf = kt & 1;
        if (kt + 1 < NCHUNK) {
            CPA(kt + 1, buf ^ 1);
            LOADB(kt + 1);
        }
        COMPUTE(buf);
        if (kt + 1 < NCHUNK) STOREB(buf ^ 1);
        CP_WAIT0();
        __syncthreads();
    }

    const int hw0 = (p0 & 1023);
#pragma unroll
    for (int ms = 0; ms < 2; ms++)
#pragma unroll
        for (int ns = 0; ns < 4; ns++) {
            int row  = o_base + warp_m * 32 + ms * 16 + (lane >> 2);
            int coln = hw0 + warp_n * 32 + ns * 8 + (lane & 3) * 2;
            float* p1 = out + (((size_t)(n_img * O_TOT + row)) << 10) + coln;
            *(float2*)p1 = make_float2(acc[ms][ns][0], acc[ms][ns][1]);
            float* p2 = p1 + ((size_t)8 << 10);
            *(float2*)p2 = make_float2(acc[ms][ns][2], acc[ms][ns][3]);
        }
}

// ---------------- launch ----------------
extern "C" void kernel_launch(void* const* d_in, const int* in_sizes, int n_in,
                              void* d_out, int out_size) {
    const float* x      = (const float*)d_in[0];
    const float* conv_w = (const float*)d_in[1];
    const float* gamma  = (const float*)d_in[2];
    const float* beta   = (const float*)d_in[3];
    const float* weight = (const float*)d_in[4];
    float* out = (float*)d_out;

    cudaFuncSetAttribute(gemm_mma, cudaFuncAttributeMaxDynamicSharedMemorySize, SMEM_GEMM);
    cudaFuncSetAttribute(conv_partial, cudaFuncAttributeMaxDynamicSharedMemorySize, 1024 * 9 * 8);

    prep_a      <<<(O_TOT * C_TOT) / 256, 256>>>(weight);
    transpose_cw<<<(K_TOT * L_TOT + 255) / 256, 256>>>(conv_w);
    conv_partial<<<dim3(8, 18), 256, 1024 * 9 * 8>>>(x);
    conv_reduce <<<(L_TOT * NPIX + 255) / 256, 256>>>();
    bn_stats    <<<9, 256>>>(gamma, beta);
    softmax_k   <<<NPIX / 256, 256>>>();
    gemm_mma    <<<dim3(NPIX / N_TILE, O_TOT / M_TILE), 256, SMEM_GEMM>>>(x, out);
}